// round 14
// baseline (speedup 1.0000x reference)
#include <cuda_runtime.h>
#include <cuda_fp16.h>
#include <cstdint>

#define SD 32
#define OC 16
#define NMAX 50000
#define EMAX 800000
#define BN_EPS 1e-5f

__device__ __half g_T2h[(size_t)NMAX * 512];
__device__ __half g_h1h[(size_t)EMAX * 32];
__device__ __half g_h2h[(size_t)EMAX * 32];
__device__ __half g_hah[(size_t)EMAX * 32];
__device__ float g_B [NMAX * OC];
__device__ float g_agg[NMAX * OC];
__device__ float g_n1[NMAX * 32];
__device__ float g_n2[NMAX * 32];
__device__ float g_w3r[32 * 512];
__device__ int   g_src[EMAX];
__device__ int   g_dst[EMAX];
__device__ int   g_eord[EMAX];
__device__ int   g_dstS[EMAX];
__device__ int   g_cnt[NMAX];
__device__ int   g_cur[NMAX];
__device__ float g_sums[4 * 64];
__device__ float g_bnp [4 * 64];
__device__ int   g_is64;
__device__ int   g_work;

typedef unsigned long long u64;

__device__ __forceinline__ u64 pk2(float lo, float hi) {
    u64 r; asm("mov.b64 %0, {%1, %2};" : "=l"(r) : "f"(lo), "f"(hi)); return r;
}
__device__ __forceinline__ float2 upk2(u64 v) {
    float2 f; asm("mov.b64 {%0, %1}, %2;" : "=f"(f.x), "=f"(f.y) : "l"(v)); return f;
}
__device__ __forceinline__ void fma2(u64& d, u64 a, u64 b) {
    asm("fma.rn.f32x2 %0, %1, %2, %0;" : "+l"(d) : "l"(a), "l"(b));
}
__device__ __forceinline__ void red_add_v4(float* addr, float4 v) {
    asm volatile("red.global.add.v4.f32 [%0], {%1, %2, %3, %4};"
                 :: "l"(addr), "f"(v.x), "f"(v.y), "f"(v.z), "f"(v.w) : "memory");
}
__device__ __forceinline__ void prefetchL2(const void* p) {
    asm volatile("prefetch.global.L2 [%0];" :: "l"(p));
}
__device__ __forceinline__ unsigned h2bits(__half2 h) {
    return *(unsigned*)&h;
}
__device__ __forceinline__ uint2 acc2half4(u64 a, u64 b) {
    float2 fa = upk2(a), fb = upk2(b);
    uint2 r;
    r.x = h2bits(__floats2half2_rn(fa.x, fa.y));
    r.y = h2bits(__floats2half2_rn(fb.x, fb.y));
    return r;
}

__global__ void k_init(const void* idx, long ewords, int nmax, int N, const float* __restrict__ w3) {
    int b = blockIdx.x, t = threadIdx.x;
    int i = b * 256 + t;
    if (i < N) g_cnt[i] = 0;
    if (b < 64) {
        int tt = b * 256 + t;
        int ii = tt >> 9, oh = tt & 511, o = oh >> 5, h = oh & 31;
        g_w3r[tt] = w3[h * 512 + ii * 16 + o];
    }
    if (b == 0) {
        g_sums[t] = 0.0f;
        if (t == 0) g_work = 0;
    }
    if (b == gridDim.x - 1) {
        __shared__ int bad;
        if (t == 0) bad = 0;
        __syncthreads();
        long s = ((long)t * 12347L) % ewords;
        long long v = ((const long long*)idx)[s];
        if (v < 0 || v >= (long long)nmax) atomicOr(&bad, 1);
        __syncthreads();
        if (t == 0) g_is64 = bad ? 0 : 1;
    }
}

__global__ void k_converthist(const void* idx, long E) {
    long e = blockIdx.x * 256L + threadIdx.x;
    if (e >= E) return;
    int s, d;
    if (g_is64) {
        const long long* p = (const long long*)idx;
        s = (int)p[e]; d = (int)p[E + e];
    } else {
        const int* p = (const int*)idx;
        s = p[e]; d = p[E + e];
    }
    g_src[e] = s;
    g_dst[e] = d;
    atomicAdd(&g_cnt[s], 1);
}

__global__ void k_scan(int n) {
    __shared__ int warpsum[32];
    int tid = threadIdx.x;
    int per = (n + 1023) / 1024;
    int beg = tid * per;
    int end = beg + per; if (end > n) end = n;
    int s = 0;
    for (int i = beg; i < end; i++) s += g_cnt[i];
    int lane = tid & 31, wid = tid >> 5;
    int v = s;
#pragma unroll
    for (int off = 1; off < 32; off <<= 1) {
        int t = __shfl_up_sync(0xffffffffu, v, off);
        if (lane >= off) v += t;
    }
    if (lane == 31) warpsum[wid] = v;
    __syncthreads();
    if (wid == 0) {
        int w = warpsum[lane];
#pragma unroll
        for (int off = 1; off < 32; off <<= 1) {
            int t = __shfl_up_sync(0xffffffffu, w, off);
            if (lane >= off) w += t;
        }
        warpsum[lane] = w;
    }
    __syncthreads();
    int run = (wid > 0 ? warpsum[wid - 1] : 0) + v - s;
    for (int i = beg; i < end; i++) {
        int c = g_cnt[i];
        g_cur[i] = run;
        run += c;
    }
}

__global__ void k_T(const float* __restrict__ x, int N) {
    extern __shared__ float sm[];
    float* ws = sm;
    float* xs = sm + 16384;
    int tid = threadIdx.x;
    for (int t = tid; t < 16384; t += 256) ws[t] = g_w3r[t];
    int vb = blockIdx.x * 32;
    for (int t = tid; t < 1024; t += 256) {
        int v = vb + (t >> 5);
        xs[t] = (v < N) ? x[(size_t)v * 32 + (t & 31)] : 0.0f;
    }
    __syncthreads();
    int w = tid >> 5, lane = tid & 31;
    u64 acc[4][8];
#pragma unroll
    for (int r = 0; r < 4; r++)
#pragma unroll
        for (int k = 0; k < 8; k++) acc[r][k] = 0ULL;
#pragma unroll 8
    for (int i = 0; i < 32; i++) {
        u64 a0 = pk2(xs[(w*4+0)*32 + i], xs[(w*4+0)*32 + i]);
        u64 a1 = pk2(xs[(w*4+1)*32 + i], xs[(w*4+1)*32 + i]);
        u64 a2 = pk2(xs[(w*4+2)*32 + i], xs[(w*4+2)*32 + i]);
        u64 a3 = pk2(xs[(w*4+3)*32 + i], xs[(w*4+3)*32 + i]);
#pragma unroll
        for (int k = 0; k < 4; k++) {
            ulonglong2 w2 = *(const ulonglong2*)&ws[i * 512 + lane * 4 + k * 128];
            fma2(acc[0][2*k], a0, w2.x); fma2(acc[0][2*k+1], a0, w2.y);
            fma2(acc[1][2*k], a1, w2.x); fma2(acc[1][2*k+1], a1, w2.y);
            fma2(acc[2][2*k], a2, w2.x); fma2(acc[2][2*k+1], a2, w2.y);
            fma2(acc[3][2*k], a3, w2.x); fma2(acc[3][2*k+1], a3, w2.y);
        }
    }
#pragma unroll
    for (int r = 0; r < 4; r++) {
        int v = vb + w * 4 + r;
        if (v < N) {
#pragma unroll
            for (int k = 0; k < 4; k++) {
                uint2 st = acc2half4(acc[r][2*k], acc[r][2*k+1]);
                *(uint2*)((char*)g_T2h + ((size_t)v * 512 + lane * 4 + k * 128) * 2) = st;
            }
        }
    }
}

__global__ void k_scatter(long E) {
    long e = blockIdx.x * 256L + threadIdx.x;
    if (e >= E) return;
    int s = g_src[e];
    int slot = atomicAdd(&g_cur[s], 1);
    g_eord[slot] = (int)e;
    g_dstS[slot] = g_dst[e];
}

// e1: 2 edges/thread streaming, write h1 fp16 (original order)
__global__ void k_e1(const float* __restrict__ A, const float* __restrict__ w,
                     const float* __restrict__ b, long E) {
    __shared__ float wsm[1024], bsm[32];
    int tid = threadIdx.x;
    long e0 = blockIdx.x * 512L + tid;
    long e1 = e0 + 256;
    bool v0 = e0 < E, v1 = e1 < E;
    const float4* p0 = (const float4*)(A + (v0 ? e0 : 0) * 32);
    const float4* p1 = (const float4*)(A + (v1 ? e1 : 0) * 32);
    prefetchL2(p0);
    prefetchL2(p1);
    for (int t = tid; t < 1024; t += 256) wsm[t] = w[t];
    if (tid < 32) bsm[tid] = b[tid];
    __syncthreads();
    u64 acc0[16], acc1[16];
#pragma unroll
    for (int j = 0; j < 16; j++) { acc0[j] = pk2(bsm[2*j], bsm[2*j+1]); acc1[j] = acc0[j]; }
#pragma unroll
    for (int q = 0; q < 8; q++) {
        float4 t0 = p0[q], t1 = p1[q];
#pragma unroll
        for (int ii = 0; ii < 4; ii++) {
            float a0v = (&t0.x)[ii];
            float a1v = (&t1.x)[ii];
            u64 s0 = pk2(a0v, a0v);
            u64 s1 = pk2(a1v, a1v);
            const ulonglong2* wrow = (const ulonglong2*)&wsm[(q * 4 + ii) * 32];
#pragma unroll
            for (int j = 0; j < 8; j++) {
                ulonglong2 w2 = wrow[j];
                fma2(acc0[2*j], s0, w2.x); fma2(acc0[2*j+1], s0, w2.y);
                fma2(acc1[2*j], s1, w2.x); fma2(acc1[2*j+1], s1, w2.y);
            }
        }
    }
    if (v0) {
        uint4* o = (uint4*)(g_h1h + e0 * 32);
#pragma unroll
        for (int k = 0; k < 4; k++) {
            uint2 a = acc2half4(acc0[4*k], acc0[4*k+1]);
            uint2 b2 = acc2half4(acc0[4*k+2], acc0[4*k+3]);
            o[k] = make_uint4(a.x, a.y, b2.x, b2.y);
        }
    }
    if (v1) {
        uint4* o = (uint4*)(g_h1h + e1 * 32);
#pragma unroll
        for (int k = 0; k < 4; k++) {
            uint2 a = acc2half4(acc1[4*k], acc1[4*k+1]);
            uint2 b2 = acc2half4(acc1[4*k+2], acc1[4*k+3]);
            o[k] = make_uint4(a.x, a.y, b2.x, b2.y);
        }
    }
}

__global__ void k_stath(int which, long nu, int stage) {
    const uint4* p = (which == 0) ? (const uint4*)g_h1h : (const uint4*)g_h2h;
    __shared__ float ssum[64];
    float s[8], q[8];
#pragma unroll
    for (int j = 0; j < 8; j++) { s[j] = 0.0f; q[j] = 0.0f; }
    long tid = blockIdx.x * 256L + threadIdx.x;
    long stride = (long)gridDim.x * 256L;
    for (long i = tid; i < nu; i += stride) {
        uint4 u = p[i];
        const __half2* hp = (const __half2*)&u;
#pragma unroll
        for (int j = 0; j < 4; j++) {
            float2 f = __half22float2(hp[j]);
            s[2*j]   += f.x; q[2*j]   += f.x * f.x;
            s[2*j+1] += f.y; q[2*j+1] += f.y * f.y;
        }
    }
#pragma unroll
    for (int off = 4; off < 32; off <<= 1) {
#pragma unroll
        for (int j = 0; j < 8; j++) {
            s[j] += __shfl_xor_sync(0xffffffffu, s[j], off);
            q[j] += __shfl_xor_sync(0xffffffffu, q[j], off);
        }
    }
    if (threadIdx.x < 64) ssum[threadIdx.x] = 0.0f;
    __syncthreads();
    int lane = threadIdx.x & 31;
    if (lane < 4) {
        int cb = lane * 8;
#pragma unroll
        for (int j = 0; j < 8; j++) {
            atomicAdd(&ssum[cb + j], s[j]);
            atomicAdd(&ssum[32 + cb + j], q[j]);
        }
    }
    __syncthreads();
    if (threadIdx.x < 64) atomicAdd(&g_sums[stage * 64 + threadIdx.x], ssum[threadIdx.x]);
}

__global__ void k_fin(int stage, const float* __restrict__ g, const float* __restrict__ be, float n) {
    int j = threadIdx.x;
    float s  = g_sums[stage * 64 + j];
    float sq = g_sums[stage * 64 + 32 + j];
    float m = s / n;
    float var = sq / n - m * m;
    float scale = g[j] * rsqrtf(var + BN_EPS);
    g_bnp[stage * 64 + j] = scale;
    g_bnp[stage * 64 + 32 + j] = be[j] - m * scale;
}

// e2: fully streaming (original order): read h1h, bn0+relu, GEMM, write h2h
__global__ void k_e2(const float* __restrict__ w, const float* __restrict__ b, long E) {
    __shared__ float wsm[1024], bsm[32], sc[32], sh[32];
    int tid = threadIdx.x;
    long k0 = blockIdx.x * 512L + tid;
    long k1 = k0 + 256;
    bool v0 = k0 < E, v1 = k1 < E;
    const uint4* r0 = (const uint4*)(g_h1h + (v0 ? k0 : 0) * 32);
    const uint4* r1 = (const uint4*)(g_h1h + (v1 ? k1 : 0) * 32);
    prefetchL2(r0);
    prefetchL2(r1);
    for (int t = tid; t < 1024; t += 256) wsm[t] = w[t];
    if (tid < 32) { bsm[tid] = b[tid]; sc[tid] = g_bnp[tid]; sh[tid] = g_bnp[32 + tid]; }
    __syncthreads();
    uint4 u0[4], u1[4];
#pragma unroll
    for (int k = 0; k < 4; k++) { u0[k] = r0[k]; u1[k] = r1[k]; }
    u64 acc0[16], acc1[16];
#pragma unroll
    for (int j = 0; j < 16; j++) { acc0[j] = pk2(bsm[2*j], bsm[2*j+1]); acc1[j] = acc0[j]; }
#pragma unroll
    for (int k = 0; k < 4; k++) {
        const __half2* h0 = (const __half2*)&u0[k];
        const __half2* h1 = (const __half2*)&u1[k];
#pragma unroll
        for (int j = 0; j < 4; j++) {
            float2 f0 = __half22float2(h0[j]);
            float2 f1 = __half22float2(h1[j]);
            int c = k * 8 + 2 * j;
            float a00 = fmaxf(f0.x * sc[c]   + sh[c],   0.0f);
            float a01 = fmaxf(f0.y * sc[c+1] + sh[c+1], 0.0f);
            float a10 = fmaxf(f1.x * sc[c]   + sh[c],   0.0f);
            float a11 = fmaxf(f1.y * sc[c+1] + sh[c+1], 0.0f);
            {
                u64 s0 = pk2(a00, a00), s1 = pk2(a10, a10);
                const ulonglong2* wrow = (const ulonglong2*)&wsm[c * 32];
#pragma unroll
                for (int jj = 0; jj < 8; jj++) {
                    ulonglong2 w2 = wrow[jj];
                    fma2(acc0[2*jj], s0, w2.x); fma2(acc0[2*jj+1], s0, w2.y);
                    fma2(acc1[2*jj], s1, w2.x); fma2(acc1[2*jj+1], s1, w2.y);
                }
            }
            {
                u64 s0 = pk2(a01, a01), s1 = pk2(a11, a11);
                const ulonglong2* wrow = (const ulonglong2*)&wsm[(c + 1) * 32];
#pragma unroll
                for (int jj = 0; jj < 8; jj++) {
                    ulonglong2 w2 = wrow[jj];
                    fma2(acc0[2*jj], s0, w2.x); fma2(acc0[2*jj+1], s0, w2.y);
                    fma2(acc1[2*jj], s1, w2.x); fma2(acc1[2*jj+1], s1, w2.y);
                }
            }
        }
    }
    if (v0) {
        uint4* o = (uint4*)(g_h2h + k0 * 32);
#pragma unroll
        for (int k = 0; k < 4; k++) {
            uint2 a = acc2half4(acc0[4*k], acc0[4*k+1]);
            uint2 b2 = acc2half4(acc0[4*k+2], acc0[4*k+3]);
            o[k] = make_uint4(a.x, a.y, b2.x, b2.y);
        }
    }
    if (v1) {
        uint4* o = (uint4*)(g_h2h + k1 * 32);
#pragma unroll
        for (int k = 0; k < 4; k++) {
            uint2 a = acc2half4(acc1[4*k], acc1[4*k+1]);
            uint2 b2 = acc2half4(acc1[4*k+2], acc1[4*k+3]);
            o[k] = make_uint4(a.x, a.y, b2.x, b2.y);
        }
    }
}

// act: gather h2h[eord[k]] (sorted), bn1+relu, write hah[k] fp16 (sorted order)
__global__ void k_act(long nu) {
    __shared__ float sc[32], sh[32];
    int tid = threadIdx.x;
    if (tid < 32) { sc[tid] = g_bnp[64 + tid]; sh[tid] = g_bnp[96 + tid]; }
    __syncthreads();
    long i = blockIdx.x * 256L + tid;
    if (i >= nu) return;
    long k = i >> 2;
    int chunk = (int)(i & 3);
    long e = g_eord[k];
    int cb = chunk * 8;
    uint4 u = ((const uint4*)g_h2h)[e * 4 + chunk];
    const __half2* hp = (const __half2*)&u;
    uint4 st;
    unsigned* sp = (unsigned*)&st;
#pragma unroll
    for (int j = 0; j < 4; j++) {
        float2 f = __half22float2(hp[j]);
        int c = cb + 2 * j;
        float o0 = fmaxf(f.x * sc[c]   + sh[c],   0.0f);
        float o1 = fmaxf(f.y * sc[c+1] + sh[c+1], 0.0f);
        sp[j] = h2bits(__floats2half2_rn(o0, o1));
    }
    ((uint4*)g_hah)[i] = st;
}

__global__ void k_rootB(const float* __restrict__ x, const float* __restrict__ rw,
                        const float* __restrict__ rb, const float* __restrict__ b3, int N) {
    __shared__ float rws[512], b3s[512], rbs[16];
    int tid = threadIdx.x;
    for (int t = tid; t < 512; t += 256) { rws[t] = rw[t]; b3s[t] = b3[t]; }
    if (tid < 16) rbs[tid] = rb[tid];
    __syncthreads();
    int v = blockIdx.x * 256 + tid;
    if (v >= N) return;
    float a[32];
    const float4* xr = (const float4*)(x + (size_t)v * 32);
#pragma unroll
    for (int k = 0; k < 8; k++) {
        float4 t4 = xr[k];
        a[4*k] = t4.x; a[4*k+1] = t4.y; a[4*k+2] = t4.z; a[4*k+3] = t4.w;
    }
    float accr[16], accb[16];
#pragma unroll
    for (int o = 0; o < 16; o++) { accr[o] = rbs[o]; accb[o] = 0.0f; }
#pragma unroll 8
    for (int i = 0; i < 32; i++) {
        float av = a[i];
#pragma unroll
        for (int o = 0; o < 16; o++) {
            accr[o] += av * rws[i * 16 + o];
            accb[o] += av * b3s[i * 16 + o];
        }
    }
#pragma unroll
    for (int o = 0; o < 16; o++) {
        g_agg[(size_t)v * 16 + o] = accr[o];
        g_B[(size_t)v * 16 + o]   = accb[o];
    }
}

// e3: persistent work-stealing warps (batch 8 nodes), half-warp per sorted edge
__global__ void k_e3(int N) {
    int tid = threadIdx.x;
    int lane = tid & 31;
    int half = lane >> 4;
    int o = lane & 15;
    int src_base = (lane & 16) | ((lane & 3) << 2);
    for (;;) {
        int base = 0;
        if (lane == 0) base = atomicAdd(&g_work, 8);
        base = __shfl_sync(0xffffffffu, base, 0);
        if (base >= N) break;
        int lim = base + 8 < N ? base + 8 : N;
        for (int v = base; v < lim; v++) {
            int start = (v > 0) ? g_cur[v - 1] : 0;
            int end = g_cur[v];
            if (start >= end) continue;
            float tf[32];
            {
                const uint4* tp = (const uint4*)((const char*)g_T2h + ((size_t)v * 512 + o * 32) * 2);
#pragma unroll
                for (int q = 0; q < 4; q++) {
                    uint4 t = tp[q];
                    const __half2* hp = (const __half2*)&t;
#pragma unroll
                    for (int j = 0; j < 4; j++) {
                        float2 f = __half22float2(hp[j]);
                        tf[q*8 + 2*j] = f.x; tf[q*8 + 2*j + 1] = f.y;
                    }
                }
            }
            float bval = g_B[(size_t)v * 16 + o];
            for (int eb = start; eb < end; eb += 2) {
                int k = eb + half;
                bool val = k < end;
                int kk = val ? k : start;
                int d = g_dstS[kk];
                const uint4* hp4 = (const uint4*)(g_hah + (size_t)kk * 32);
                float acc = bval;
#pragma unroll
                for (int q = 0; q < 4; q++) {
                    uint4 u = hp4[q];
                    const __half2* hp = (const __half2*)&u;
#pragma unroll
                    for (int j = 0; j < 4; j++) {
                        float2 f = __half22float2(hp[j]);
                        int c = q * 8 + 2 * j;
                        acc += f.x * tf[c] + f.y * tf[c + 1];
                    }
                }
                float m0 = __shfl_sync(0xffffffffu, acc, src_base + 0);
                float m1 = __shfl_sync(0xffffffffu, acc, src_base + 1);
                float m2 = __shfl_sync(0xffffffffu, acc, src_base + 2);
                float m3 = __shfl_sync(0xffffffffu, acc, src_base + 3);
                if (val && (lane & 15) < 4) {
                    red_add_v4(&g_agg[(size_t)d * 16 + (lane & 3) * 4], make_float4(m0, m1, m2, m3));
                }
            }
        }
    }
}

__global__ void k_stat(int which, long n4, int stage) {
    const float4* d = (which == 1) ? (const float4*)g_n1 : (const float4*)g_n2;
    __shared__ float ssum[64];
    float* out = &g_sums[stage * 64];
    long tid = blockIdx.x * 256L + threadIdx.x;
    long stride = (long)gridDim.x * 256L;
    float4 s = make_float4(0,0,0,0), q = make_float4(0,0,0,0);
    for (long i = tid; i < n4; i += stride) {
        float4 v = d[i];
        s.x += v.x; s.y += v.y; s.z += v.z; s.w += v.w;
        q.x += v.x*v.x; q.y += v.y*v.y; q.z += v.z*v.z; q.w += v.w*v.w;
    }
#pragma unroll
    for (int off = 8; off < 32; off <<= 1) {
        s.x += __shfl_xor_sync(0xffffffffu, s.x, off);
        s.y += __shfl_xor_sync(0xffffffffu, s.y, off);
        s.z += __shfl_xor_sync(0xffffffffu, s.z, off);
        s.w += __shfl_xor_sync(0xffffffffu, s.w, off);
        q.x += __shfl_xor_sync(0xffffffffu, q.x, off);
        q.y += __shfl_xor_sync(0xffffffffu, q.y, off);
        q.z += __shfl_xor_sync(0xffffffffu, q.z, off);
        q.w += __shfl_xor_sync(0xffffffffu, q.w, off);
    }
    if (threadIdx.x < 64) ssum[threadIdx.x] = 0.0f;
    __syncthreads();
    int lane = threadIdx.x & 31;
    if (lane < 8) {
        int cb = lane * 4;
        atomicAdd(&ssum[cb+0], s.x); atomicAdd(&ssum[cb+1], s.y);
        atomicAdd(&ssum[cb+2], s.z); atomicAdd(&ssum[cb+3], s.w);
        atomicAdd(&ssum[32+cb+0], q.x); atomicAdd(&ssum[32+cb+1], q.y);
        atomicAdd(&ssum[32+cb+2], q.z); atomicAdd(&ssum[32+cb+3], q.w);
    }
    __syncthreads();
    if (threadIdx.x < 64) atomicAdd(&out[threadIdx.x], ssum[threadIdx.x]);
}

#define GEMM32_BODY(NI, OUT_PTR) \
    u64 acc2[16]; \
    _Pragma("unroll") for (int j = 0; j < 16; j++) acc2[j] = pk2(bsm[2*j], bsm[2*j+1]); \
    _Pragma("unroll 8") for (int i = 0; i < NI; i++) { \
        u64 av = pk2(a[i], a[i]); \
        const ulonglong2* wrow = (const ulonglong2*)&wsm[i * 32]; \
        _Pragma("unroll") for (int j = 0; j < 8; j++) { \
            ulonglong2 w2 = wrow[j]; \
            fma2(acc2[2*j], av, w2.x); fma2(acc2[2*j+1], av, w2.y); } } \
    float4* outr = (float4*)(OUT_PTR); \
    _Pragma("unroll") for (int k = 0; k < 8; k++) { \
        float2 u0 = upk2(acc2[2*k]), u1 = upk2(acc2[2*k+1]); \
        outr[k] = make_float4(u0.x, u0.y, u1.x, u1.y); }

__global__ void k_own1(const float* __restrict__ x, const float* __restrict__ w,
                       const float* __restrict__ b, int N) {
    __shared__ float wsm[1536], bsm[32];
    int tid = threadIdx.x;
    for (int t = tid; t < 1536; t += 256) wsm[t] = w[t];
    if (tid < 32) bsm[tid] = b[tid];
    __syncthreads();
    int v = blockIdx.x * 256 + tid;
    if (v >= N) return;
    float a[48];
    const float4* xr = (const float4*)(x + (size_t)v * 32);
#pragma unroll
    for (int k = 0; k < 8; k++) {
        float4 t4 = xr[k];
        a[4*k] = t4.x; a[4*k+1] = t4.y; a[4*k+2] = t4.z; a[4*k+3] = t4.w;
    }
    const float4* gr = (const float4*)(g_agg + (size_t)v * 16);
#pragma unroll
    for (int k = 0; k < 4; k++) {
        float4 t4 = gr[k];
        a[32+4*k] = t4.x; a[32+4*k+1] = t4.y; a[32+4*k+2] = t4.z; a[32+4*k+3] = t4.w;
    }
    GEMM32_BODY(48, g_n1 + (size_t)v * 32)
}

__global__ void k_own2(const float* __restrict__ w, const float* __restrict__ b, int N) {
    __shared__ float wsm[1024], bsm[32], sc[32], sh[32];
    int tid = threadIdx.x;
    for (int t = tid; t < 1024; t += 256) wsm[t] = w[t];
    if (tid < 32) { bsm[tid] = b[tid]; sc[tid] = g_bnp[128 + tid]; sh[tid] = g_bnp[160 + tid]; }
    __syncthreads();
    int v = blockIdx.x * 256 + tid;
    if (v >= N) return;
    float a[32];
    const float4* ar = (const float4*)(g_n1 + (size_t)v * 32);
#pragma unroll
    for (int k = 0; k < 8; k++) {
        float4 t4 = ar[k];
        a[4*k+0] = fmaxf(t4.x * sc[4*k+0] + sh[4*k+0], 0.0f);
        a[4*k+1] = fmaxf(t4.y * sc[4*k+1] + sh[4*k+1], 0.0f);
        a[4*k+2] = fmaxf(t4.z * sc[4*k+2] + sh[4*k+2], 0.0f);
        a[4*k+3] = fmaxf(t4.w * sc[4*k+3] + sh[4*k+3], 0.0f);
    }
    GEMM32_BODY(32, g_n2 + (size_t)v * 32)
}

__global__ void k_own3(const float* __restrict__ w, const float* __restrict__ b,
                       float* __restrict__ out, int N) {
    __shared__ float wsm[1024], bsm[32], sc[32], sh[32];
    int tid = threadIdx.x;
    for (int t = tid; t < 1024; t += 256) wsm[t] = w[t];
    if (tid < 32) { bsm[tid] = b[tid]; sc[tid] = g_bnp[192 + tid]; sh[tid] = g_bnp[224 + tid]; }
    __syncthreads();
    int v = blockIdx.x * 256 + tid;
    if (v >= N) return;
    float a[32];
    const float4* ar = (const float4*)(g_n2 + (size_t)v * 32);
#pragma unroll
    for (int k = 0; k < 8; k++) {
        float4 t4 = ar[k];
        a[4*k+0] = fmaxf(t4.x * sc[4*k+0] + sh[4*k+0], 0.0f);
        a[4*k+1] = fmaxf(t4.y * sc[4*k+1] + sh[4*k+1], 0.0f);
        a[4*k+2] = fmaxf(t4.z * sc[4*k+2] + sh[4*k+2], 0.0f);
        a[4*k+3] = fmaxf(t4.w * sc[4*k+3] + sh[4*k+3], 0.0f);
    }
    GEMM32_BODY(32, out + (size_t)v * 32)
}

extern "C" void kernel_launch(void* const* d_in, const int* in_sizes, int n_in,
                              void* d_out, int out_size) {
    const float* x    = (const float*)d_in[0];
    const float* ea   = (const float*)d_in[1];
    const void*  ei   = d_in[2];
    const float* mw1  = (const float*)d_in[3];
    const float* mb1  = (const float*)d_in[4];
    const float* mg1  = (const float*)d_in[5];
    const float* mbe1 = (const float*)d_in[6];
    const float* mw2  = (const float*)d_in[7];
    const float* mb2  = (const float*)d_in[8];
    const float* mg2  = (const float*)d_in[9];
    const float* mbe2 = (const float*)d_in[10];
    const float* mw3  = (const float*)d_in[11];
    const float* mb3  = (const float*)d_in[12];
    const float* rw   = (const float*)d_in[13];
    const float* rb   = (const float*)d_in[14];
    const float* ow1  = (const float*)d_in[15];
    const float* ob1  = (const float*)d_in[16];
    const float* og1  = (const float*)d_in[17];
    const float* obe1 = (const float*)d_in[18];
    const float* ow2  = (const float*)d_in[19];
    const float* ob2  = (const float*)d_in[20];
    const float* og2  = (const float*)d_in[21];
    const float* obe2 = (const float*)d_in[22];
    const float* ow3  = (const float*)d_in[23];
    const float* ob3  = (const float*)d_in[24];
    float* out = (float*)d_out;

    int  N = in_sizes[0] / SD;
    long E = (long)in_sizes[1] / SD;

    cudaFuncSetAttribute(k_T, cudaFuncAttributeMaxDynamicSharedMemorySize, 69632);

    int nb256  = (N + 255) / 256;
    long eb256 = (E + 255) / 256;
    long eb2   = (E + 511) / 512;
    long nu    = E * 4;

    k_init<<<nb256, 256>>>(ei, E, N, N, mw3);          // 1
    k_converthist<<<(unsigned)eb256, 256>>>(ei, E);    // 2
    k_scan<<<1, 1024>>>(N);                            // 3
    k_T<<<(N + 31) / 32, 256, 69632>>>(x, N);          // 4: PROFILED (measurement)
    k_scatter<<<(unsigned)eb256, 256>>>(E);            // 5
    k_e1<<<(unsigned)eb2, 256>>>(ea, mw1, mb1, E);     // 6
    k_stath<<<296, 256>>>(0, nu, 0);
    k_fin<<<1, 32>>>(0, mg1, mbe1, (float)E);
    k_e2<<<(unsigned)eb2, 256>>>(mw2, mb2, E);
    k_stath<<<296, 256>>>(1, nu, 1);
    k_fin<<<1, 32>>>(1, mg2, mbe2, (float)E);
    k_rootB<<<nb256, 256>>>(x, rw, rb, mb3, N);
    k_act<<<(unsigned)((nu + 255) / 256), 256>>>(nu);
    k_e3<<<1184, 256>>>(N);
    k_own1<<<nb256, 256>>>(x, ow1, ob1, N);
    k_stat<<<148, 256>>>(1, (long)N * 8, 2);
    k_fin<<<1, 32>>>(2, og1, obe1, (float)N);
    k_own2<<<nb256, 256>>>(ow2, ob2, N);
    k_stat<<<148, 256>>>(2, (long)N * 8, 3);
    k_fin<<<1, 32>>>(3, og2, obe2, (float)N);
    k_own3<<<nb256, 256>>>(ow3, ob3, out, N);
}

// round 15
// speedup vs baseline: 1.0384x; 1.0384x over previous
#include <cuda_runtime.h>
#include <cuda_fp16.h>
#include <cstdint>

#define SD 32
#define OC 16
#define NMAX 50000
#define EMAX 800000
#define BN_EPS 1e-5f

__device__ __half g_T2h[(size_t)NMAX * 512];
__device__ __half g_h1h[(size_t)EMAX * 32];
__device__ __half g_h2h[(size_t)EMAX * 32];
__device__ __half g_hah[(size_t)EMAX * 32];
__device__ float g_B [NMAX * OC];
__device__ float g_agg[NMAX * OC];
__device__ float g_n1[NMAX * 32];
__device__ float g_n2[NMAX * 32];
__device__ float g_w3r[32 * 512];
__device__ int   g_src[EMAX];
__device__ int   g_dst[EMAX];
__device__ int   g_eord[EMAX];
__device__ int   g_dstS[EMAX];
__device__ int   g_cnt[NMAX];
__device__ int   g_cur[NMAX];
__device__ float g_sums[4 * 64];
__device__ int   g_is64;
__device__ int   g_work;

typedef unsigned long long u64;

__device__ __forceinline__ u64 pk2(float lo, float hi) {
    u64 r; asm("mov.b64 %0, {%1, %2};" : "=l"(r) : "f"(lo), "f"(hi)); return r;
}
__device__ __forceinline__ float2 upk2(u64 v) {
    float2 f; asm("mov.b64 {%0, %1}, %2;" : "=f"(f.x), "=f"(f.y) : "l"(v)); return f;
}
__device__ __forceinline__ void fma2(u64& d, u64 a, u64 b) {
    asm("fma.rn.f32x2 %0, %1, %2, %0;" : "+l"(d) : "l"(a), "l"(b));
}
__device__ __forceinline__ void red_add_v4(float* addr, float4 v) {
    asm volatile("red.global.add.v4.f32 [%0], {%1, %2, %3, %4};"
                 :: "l"(addr), "f"(v.x), "f"(v.y), "f"(v.z), "f"(v.w) : "memory");
}
__device__ __forceinline__ void prefetchL2(const void* p) {
    asm volatile("prefetch.global.L2 [%0];" :: "l"(p));
}
__device__ __forceinline__ unsigned h2bits(__half2 h) {
    return *(unsigned*)&h;
}
__device__ __forceinline__ uint2 acc2half4(u64 a, u64 b) {
    float2 fa = upk2(a), fb = upk2(b);
    uint2 r;
    r.x = h2bits(__floats2half2_rn(fa.x, fa.y));
    r.y = h2bits(__floats2half2_rn(fb.x, fb.y));
    return r;
}
// inline BN param computation from g_sums stage (thread j < 32)
__device__ __forceinline__ void bn_inline(int stage, const float* g, const float* be,
                                          float n, int j, float* sc, float* sh) {
    float s  = g_sums[stage * 64 + j];
    float sq = g_sums[stage * 64 + 32 + j];
    float m = s / n;
    float var = sq / n - m * m;
    float scale = g[j] * rsqrtf(var + BN_EPS);
    sc[j] = scale;
    sh[j] = be[j] - m * scale;
}

__global__ void k_init(const void* idx, long ewords, int nmax, int N, const float* __restrict__ w3) {
    int b = blockIdx.x, t = threadIdx.x;
    int i = b * 256 + t;
    if (i < N) g_cnt[i] = 0;
    if (b < 64) {
        int tt = b * 256 + t;
        int ii = tt >> 9, oh = tt & 511, o = oh >> 5, h = oh & 31;
        g_w3r[tt] = w3[h * 512 + ii * 16 + o];
    }
    if (b == 0) {
        g_sums[t] = 0.0f;
        if (t == 0) g_work = 0;
    }
    if (b == gridDim.x - 1) {
        __shared__ int bad;
        if (t == 0) bad = 0;
        __syncthreads();
        long s = ((long)t * 12347L) % ewords;
        long long v = ((const long long*)idx)[s];
        if (v < 0 || v >= (long long)nmax) atomicOr(&bad, 1);
        __syncthreads();
        if (t == 0) g_is64 = bad ? 0 : 1;
    }
}

__global__ void k_converthist(const void* idx, long E) {
    long e = blockIdx.x * 256L + threadIdx.x;
    if (e >= E) return;
    int s, d;
    if (g_is64) {
        const long long* p = (const long long*)idx;
        s = (int)p[e]; d = (int)p[E + e];
    } else {
        const int* p = (const int*)idx;
        s = p[e]; d = p[E + e];
    }
    g_src[e] = s;
    g_dst[e] = d;
    atomicAdd(&g_cnt[s], 1);
}

__global__ void k_scan(int n) {
    __shared__ int warpsum[32];
    int tid = threadIdx.x;
    int per = (n + 1023) / 1024;
    int beg = tid * per;
    int end = beg + per; if (end > n) end = n;
    int s = 0;
    for (int i = beg; i < end; i++) s += g_cnt[i];
    int lane = tid & 31, wid = tid >> 5;
    int v = s;
#pragma unroll
    for (int off = 1; off < 32; off <<= 1) {
        int t = __shfl_up_sync(0xffffffffu, v, off);
        if (lane >= off) v += t;
    }
    if (lane == 31) warpsum[wid] = v;
    __syncthreads();
    if (wid == 0) {
        int w = warpsum[lane];
#pragma unroll
        for (int off = 1; off < 32; off <<= 1) {
            int t = __shfl_up_sync(0xffffffffu, w, off);
            if (lane >= off) w += t;
        }
        warpsum[lane] = w;
    }
    __syncthreads();
    int run = (wid > 0 ? warpsum[wid - 1] : 0) + v - s;
    for (int i = beg; i < end; i++) {
        int c = g_cnt[i];
        g_cur[i] = run;
        run += c;
    }
}

// k_T fused with rootB: T2h = x @ w3r (fp16), agg init = x@rw + rb, B = x@b3
__global__ void k_T(const float* __restrict__ x, const float* __restrict__ rw,
                    const float* __restrict__ rb, const float* __restrict__ b3, int N) {
    extern __shared__ float sm[];
    float* ws  = sm;             // 16384
    float* xs  = sm + 16384;     // 1024
    float* rws = sm + 17408;     // 512
    float* b3s = sm + 17920;     // 512
    float* rbs = sm + 18432;     // 16
    int tid = threadIdx.x;
    for (int t = tid; t < 16384; t += 256) ws[t] = g_w3r[t];
    for (int t = tid; t < 512; t += 256) { rws[t] = rw[t]; b3s[t] = b3[t]; }
    if (tid < 16) rbs[tid] = rb[tid];
    int vb = blockIdx.x * 32;
    for (int t = tid; t < 1024; t += 256) {
        int v = vb + (t >> 5);
        xs[t] = (v < N) ? x[(size_t)v * 32 + (t & 31)] : 0.0f;
    }
    __syncthreads();
    int w = tid >> 5, lane = tid & 31;
    u64 acc[4][8];
#pragma unroll
    for (int r = 0; r < 4; r++)
#pragma unroll
        for (int k = 0; k < 8; k++) acc[r][k] = 0ULL;
#pragma unroll 8
    for (int i = 0; i < 32; i++) {
        u64 a0 = pk2(xs[(w*4+0)*32 + i], xs[(w*4+0)*32 + i]);
        u64 a1 = pk2(xs[(w*4+1)*32 + i], xs[(w*4+1)*32 + i]);
        u64 a2 = pk2(xs[(w*4+2)*32 + i], xs[(w*4+2)*32 + i]);
        u64 a3 = pk2(xs[(w*4+3)*32 + i], xs[(w*4+3)*32 + i]);
#pragma unroll
        for (int k = 0; k < 4; k++) {
            ulonglong2 w2 = *(const ulonglong2*)&ws[i * 512 + lane * 4 + k * 128];
            fma2(acc[0][2*k], a0, w2.x); fma2(acc[0][2*k+1], a0, w2.y);
            fma2(acc[1][2*k], a1, w2.x); fma2(acc[1][2*k+1], a1, w2.y);
            fma2(acc[2][2*k], a2, w2.x); fma2(acc[2][2*k+1], a2, w2.y);
            fma2(acc[3][2*k], a3, w2.x); fma2(acc[3][2*k+1], a3, w2.y);
        }
    }
#pragma unroll
    for (int r = 0; r < 4; r++) {
        int v = vb + w * 4 + r;
        if (v < N) {
#pragma unroll
            for (int k = 0; k < 4; k++) {
                uint2 st = acc2half4(acc[r][2*k], acc[r][2*k+1]);
                *(uint2*)((char*)g_T2h + ((size_t)v * 512 + lane * 4 + k * 128) * 2) = st;
            }
        }
    }
    // rootB epilogue: 8 threads/node, 2 (root,B) outputs each
    {
        int node = tid >> 3;           // 0..31
        int oi = (tid & 7) * 2;        // 0,2,..,14
        int v = vb + node;
        if (v < N) {
            const float* xr = &xs[node * 32];
            float r0 = rbs[oi], r1 = rbs[oi + 1];
            float b0 = 0.0f, b1 = 0.0f;
#pragma unroll 8
            for (int i = 0; i < 32; i++) {
                float av = xr[i];
                r0 += av * rws[i * 16 + oi];
                r1 += av * rws[i * 16 + oi + 1];
                b0 += av * b3s[i * 16 + oi];
                b1 += av * b3s[i * 16 + oi + 1];
            }
            g_agg[(size_t)v * 16 + oi]     = r0;
            g_agg[(size_t)v * 16 + oi + 1] = r1;
            g_B[(size_t)v * 16 + oi]       = b0;
            g_B[(size_t)v * 16 + oi + 1]   = b1;
        }
    }
}

__global__ void k_scatter(long E) {
    long e = blockIdx.x * 256L + threadIdx.x;
    if (e >= E) return;
    int s = g_src[e];
    int slot = atomicAdd(&g_cur[s], 1);
    g_eord[slot] = (int)e;
    g_dstS[slot] = g_dst[e];
}

__global__ void k_e1(const float* __restrict__ A, const float* __restrict__ w,
                     const float* __restrict__ b, long E) {
    __shared__ float wsm[1024], bsm[32];
    int tid = threadIdx.x;
    long e0 = blockIdx.x * 512L + tid;
    long e1 = e0 + 256;
    bool v0 = e0 < E, v1 = e1 < E;
    const float4* p0 = (const float4*)(A + (v0 ? e0 : 0) * 32);
    const float4* p1 = (const float4*)(A + (v1 ? e1 : 0) * 32);
    prefetchL2(p0);
    prefetchL2(p1);
    for (int t = tid; t < 1024; t += 256) wsm[t] = w[t];
    if (tid < 32) bsm[tid] = b[tid];
    __syncthreads();
    u64 acc0[16], acc1[16];
#pragma unroll
    for (int j = 0; j < 16; j++) { acc0[j] = pk2(bsm[2*j], bsm[2*j+1]); acc1[j] = acc0[j]; }
#pragma unroll
    for (int q = 0; q < 8; q++) {
        float4 t0 = p0[q], t1 = p1[q];
#pragma unroll
        for (int ii = 0; ii < 4; ii++) {
            float a0v = (&t0.x)[ii];
            float a1v = (&t1.x)[ii];
            u64 s0 = pk2(a0v, a0v);
            u64 s1 = pk2(a1v, a1v);
            const ulonglong2* wrow = (const ulonglong2*)&wsm[(q * 4 + ii) * 32];
#pragma unroll
            for (int j = 0; j < 8; j++) {
                ulonglong2 w2 = wrow[j];
                fma2(acc0[2*j], s0, w2.x); fma2(acc0[2*j+1], s0, w2.y);
                fma2(acc1[2*j], s1, w2.x); fma2(acc1[2*j+1], s1, w2.y);
            }
        }
    }
    if (v0) {
        uint4* o = (uint4*)(g_h1h + e0 * 32);
#pragma unroll
        for (int k = 0; k < 4; k++) {
            uint2 a = acc2half4(acc0[4*k], acc0[4*k+1]);
            uint2 b2 = acc2half4(acc0[4*k+2], acc0[4*k+3]);
            o[k] = make_uint4(a.x, a.y, b2.x, b2.y);
        }
    }
    if (v1) {
        uint4* o = (uint4*)(g_h1h + e1 * 32);
#pragma unroll
        for (int k = 0; k < 4; k++) {
            uint2 a = acc2half4(acc1[4*k], acc1[4*k+1]);
            uint2 b2 = acc2half4(acc1[4*k+2], acc1[4*k+3]);
            o[k] = make_uint4(a.x, a.y, b2.x, b2.y);
        }
    }
}

__global__ void k_stath(int which, long nu, int stage) {
    const uint4* p = (which == 0) ? (const uint4*)g_h1h : (const uint4*)g_h2h;
    __shared__ float ssum[64];
    float s[8], q[8];
#pragma unroll
    for (int j = 0; j < 8; j++) { s[j] = 0.0f; q[j] = 0.0f; }
    long tid = blockIdx.x * 256L + threadIdx.x;
    long stride = (long)gridDim.x * 256L;
    for (long i = tid; i < nu; i += stride) {
        uint4 u = p[i];
        const __half2* hp = (const __half2*)&u;
#pragma unroll
        for (int j = 0; j < 4; j++) {
            float2 f = __half22float2(hp[j]);
            s[2*j]   += f.x; q[2*j]   += f.x * f.x;
            s[2*j+1] += f.y; q[2*j+1] += f.y * f.y;
        }
    }
#pragma unroll
    for (int off = 4; off < 32; off <<= 1) {
#pragma unroll
        for (int j = 0; j < 8; j++) {
            s[j] += __shfl_xor_sync(0xffffffffu, s[j], off);
            q[j] += __shfl_xor_sync(0xffffffffu, q[j], off);
        }
    }
    if (threadIdx.x < 64) ssum[threadIdx.x] = 0.0f;
    __syncthreads();
    int lane = threadIdx.x & 31;
    if (lane < 4) {
        int cb = lane * 8;
#pragma unroll
        for (int j = 0; j < 8; j++) {
            atomicAdd(&ssum[cb + j], s[j]);
            atomicAdd(&ssum[32 + cb + j], q[j]);
        }
    }
    __syncthreads();
    if (threadIdx.x < 64) atomicAdd(&g_sums[stage * 64 + threadIdx.x], ssum[threadIdx.x]);
}

// e2: streaming; BN stage 0 computed inline from g_sums
__global__ void k_e2(const float* __restrict__ w, const float* __restrict__ b,
                     const float* __restrict__ g1, const float* __restrict__ be1, long E) {
    __shared__ float wsm[1024], bsm[32], sc[32], sh[32];
    int tid = threadIdx.x;
    long k0 = blockIdx.x * 512L + tid;
    long k1 = k0 + 256;
    bool v0 = k0 < E, v1 = k1 < E;
    const uint4* r0 = (const uint4*)(g_h1h + (v0 ? k0 : 0) * 32);
    const uint4* r1 = (const uint4*)(g_h1h + (v1 ? k1 : 0) * 32);
    prefetchL2(r0);
    prefetchL2(r1);
    for (int t = tid; t < 1024; t += 256) wsm[t] = w[t];
    if (tid < 32) { bsm[tid] = b[tid]; bn_inline(0, g1, be1, (float)E, tid, sc, sh); }
    __syncthreads();
    uint4 u0[4], u1[4];
#pragma unroll
    for (int k = 0; k < 4; k++) { u0[k] = r0[k]; u1[k] = r1[k]; }
    u64 acc0[16], acc1[16];
#pragma unroll
    for (int j = 0; j < 16; j++) { acc0[j] = pk2(bsm[2*j], bsm[2*j+1]); acc1[j] = acc0[j]; }
#pragma unroll
    for (int k = 0; k < 4; k++) {
        const __half2* h0 = (const __half2*)&u0[k];
        const __half2* h1 = (const __half2*)&u1[k];
#pragma unroll
        for (int j = 0; j < 4; j++) {
            float2 f0 = __half22float2(h0[j]);
            float2 f1 = __half22float2(h1[j]);
            int c = k * 8 + 2 * j;
            float a00 = fmaxf(f0.x * sc[c]   + sh[c],   0.0f);
            float a01 = fmaxf(f0.y * sc[c+1] + sh[c+1], 0.0f);
            float a10 = fmaxf(f1.x * sc[c]   + sh[c],   0.0f);
            float a11 = fmaxf(f1.y * sc[c+1] + sh[c+1], 0.0f);
            {
                u64 s0 = pk2(a00, a00), s1 = pk2(a10, a10);
                const ulonglong2* wrow = (const ulonglong2*)&wsm[c * 32];
#pragma unroll
                for (int jj = 0; jj < 8; jj++) {
                    ulonglong2 w2 = wrow[jj];
                    fma2(acc0[2*jj], s0, w2.x); fma2(acc0[2*jj+1], s0, w2.y);
                    fma2(acc1[2*jj], s1, w2.x); fma2(acc1[2*jj+1], s1, w2.y);
                }
            }
            {
                u64 s0 = pk2(a01, a01), s1 = pk2(a11, a11);
                const ulonglong2* wrow = (const ulonglong2*)&wsm[(c + 1) * 32];
#pragma unroll
                for (int jj = 0; jj < 8; jj++) {
                    ulonglong2 w2 = wrow[jj];
                    fma2(acc0[2*jj], s0, w2.x); fma2(acc0[2*jj+1], s0, w2.y);
                    fma2(acc1[2*jj], s1, w2.x); fma2(acc1[2*jj+1], s1, w2.y);
                }
            }
        }
    }
    if (v0) {
        uint4* o = (uint4*)(g_h2h + k0 * 32);
#pragma unroll
        for (int k = 0; k < 4; k++) {
            uint2 a = acc2half4(acc0[4*k], acc0[4*k+1]);
            uint2 b2 = acc2half4(acc0[4*k+2], acc0[4*k+3]);
            o[k] = make_uint4(a.x, a.y, b2.x, b2.y);
        }
    }
    if (v1) {
        uint4* o = (uint4*)(g_h2h + k1 * 32);
#pragma unroll
        for (int k = 0; k < 4; k++) {
            uint2 a = acc2half4(acc1[4*k], acc1[4*k+1]);
            uint2 b2 = acc2half4(acc1[4*k+2], acc1[4*k+3]);
            o[k] = make_uint4(a.x, a.y, b2.x, b2.y);
        }
    }
}

// act: gather h2h[eord[k]], BN stage 1 inline, write hah sorted fp16
__global__ void k_act(const float* __restrict__ g2, const float* __restrict__ be2,
                      long nu, float En) {
    __shared__ float sc[32], sh[32];
    int tid = threadIdx.x;
    if (tid < 32) bn_inline(1, g2, be2, En, tid, sc, sh);
    __syncthreads();
    long i = blockIdx.x * 256L + tid;
    if (i >= nu) return;
    long k = i >> 2;
    int chunk = (int)(i & 3);
    long e = g_eord[k];
    int cb = chunk * 8;
    uint4 u = ((const uint4*)g_h2h)[e * 4 + chunk];
    const __half2* hp = (const __half2*)&u;
    uint4 st;
    unsigned* sp = (unsigned*)&st;
#pragma unroll
    for (int j = 0; j < 4; j++) {
        float2 f = __half22float2(hp[j]);
        int c = cb + 2 * j;
        float o0 = fmaxf(f.x * sc[c]   + sh[c],   0.0f);
        float o1 = fmaxf(f.y * sc[c+1] + sh[c+1], 0.0f);
        sp[j] = h2bits(__floats2half2_rn(o0, o1));
    }
    ((uint4*)g_hah)[i] = st;
}

// e3: persistent work-stealing warps, half-warp per sorted edge
__global__ void k_e3(int N) {
    int tid = threadIdx.x;
    int lane = tid & 31;
    int half = lane >> 4;
    int o = lane & 15;
    int src_base = (lane & 16) | ((lane & 3) << 2);
    for (;;) {
        int base = 0;
        if (lane == 0) base = atomicAdd(&g_work, 8);
        base = __shfl_sync(0xffffffffu, base, 0);
        if (base >= N) break;
        int lim = base + 8 < N ? base + 8 : N;
        for (int v = base; v < lim; v++) {
            int start = (v > 0) ? g_cur[v - 1] : 0;
            int end = g_cur[v];
            if (start >= end) continue;
            float tf[32];
            {
                const uint4* tp = (const uint4*)((const char*)g_T2h + ((size_t)v * 512 + o * 32) * 2);
#pragma unroll
                for (int q = 0; q < 4; q++) {
                    uint4 t = tp[q];
                    const __half2* hp = (const __half2*)&t;
#pragma unroll
                    for (int j = 0; j < 4; j++) {
                        float2 f = __half22float2(hp[j]);
                        tf[q*8 + 2*j] = f.x; tf[q*8 + 2*j + 1] = f.y;
                    }
                }
            }
            float bval = g_B[(size_t)v * 16 + o];
            for (int eb = start; eb < end; eb += 2) {
                int k = eb + half;
                bool val = k < end;
                int kk = val ? k : start;
                int d = g_dstS[kk];
                const uint4* hp4 = (const uint4*)(g_hah + (size_t)kk * 32);
                float acc = bval;
#pragma unroll
                for (int q = 0; q < 4; q++) {
                    uint4 u = hp4[q];
                    const __half2* hp = (const __half2*)&u;
#pragma unroll
                    for (int j = 0; j < 4; j++) {
                        float2 f = __half22float2(hp[j]);
                        int c = q * 8 + 2 * j;
                        acc += f.x * tf[c] + f.y * tf[c + 1];
                    }
                }
                float m0 = __shfl_sync(0xffffffffu, acc, src_base + 0);
                float m1 = __shfl_sync(0xffffffffu, acc, src_base + 1);
                float m2 = __shfl_sync(0xffffffffu, acc, src_base + 2);
                float m3 = __shfl_sync(0xffffffffu, acc, src_base + 3);
                if (val && (lane & 15) < 4) {
                    red_add_v4(&g_agg[(size_t)d * 16 + (lane & 3) * 4], make_float4(m0, m1, m2, m3));
                }
            }
        }
    }
}

__global__ void k_stat(int which, long n4, int stage) {
    const float4* d = (which == 1) ? (const float4*)g_n1 : (const float4*)g_n2;
    __shared__ float ssum[64];
    float* out = &g_sums[stage * 64];
    long tid = blockIdx.x * 256L + threadIdx.x;
    long stride = (long)gridDim.x * 256L;
    float4 s = make_float4(0,0,0,0), q = make_float4(0,0,0,0);
    for (long i = tid; i < n4; i += stride) {
        float4 v = d[i];
        s.x += v.x; s.y += v.y; s.z += v.z; s.w += v.w;
        q.x += v.x*v.x; q.y += v.y*v.y; q.z += v.z*v.z; q.w += v.w*v.w;
    }
#pragma unroll
    for (int off = 8; off < 32; off <<= 1) {
        s.x += __shfl_xor_sync(0xffffffffu, s.x, off);
        s.y += __shfl_xor_sync(0xffffffffu, s.y, off);
        s.z += __shfl_xor_sync(0xffffffffu, s.z, off);
        s.w += __shfl_xor_sync(0xffffffffu, s.w, off);
        q.x += __shfl_xor_sync(0xffffffffu, q.x, off);
        q.y += __shfl_xor_sync(0xffffffffu, q.y, off);
        q.z += __shfl_xor_sync(0xffffffffu, q.z, off);
        q.w += __shfl_xor_sync(0xffffffffu, q.w, off);
    }
    if (threadIdx.x < 64) ssum[threadIdx.x] = 0.0f;
    __syncthreads();
    int lane = threadIdx.x & 31;
    if (lane < 8) {
        int cb = lane * 4;
        atomicAdd(&ssum[cb+0], s.x); atomicAdd(&ssum[cb+1], s.y);
        atomicAdd(&ssum[cb+2], s.z); atomicAdd(&ssum[cb+3], s.w);
        atomicAdd(&ssum[32+cb+0], q.x); atomicAdd(&ssum[32+cb+1], q.y);
        atomicAdd(&ssum[32+cb+2], q.z); atomicAdd(&ssum[32+cb+3], q.w);
    }
    __syncthreads();
    if (threadIdx.x < 64) atomicAdd(&out[threadIdx.x], ssum[threadIdx.x]);
}

#define GEMM32_BODY(NI, OUT_PTR) \
    u64 acc2[16]; \
    _Pragma("unroll") for (int j = 0; j < 16; j++) acc2[j] = pk2(bsm[2*j], bsm[2*j+1]); \
    _Pragma("unroll 8") for (int i = 0; i < NI; i++) { \
        u64 av = pk2(a[i], a[i]); \
        const ulonglong2* wrow = (const ulonglong2*)&wsm[i * 32]; \
        _Pragma("unroll") for (int j = 0; j < 8; j++) { \
            ulonglong2 w2 = wrow[j]; \
            fma2(acc2[2*j], av, w2.x); fma2(acc2[2*j+1], av, w2.y); } } \
    float4* outr = (float4*)(OUT_PTR); \
    _Pragma("unroll") for (int k = 0; k < 8; k++) { \
        float2 u0 = upk2(acc2[2*k]), u1 = upk2(acc2[2*k+1]); \
        outr[k] = make_float4(u0.x, u0.y, u1.x, u1.y); }

__global__ void k_own1(const float* __restrict__ x, const float* __restrict__ w,
                       const float* __restrict__ b, int N) {
    __shared__ float wsm[1536], bsm[32];
    int tid = threadIdx.x;
    for (int t = tid; t < 1536; t += 256) wsm[t] = w[t];
    if (tid < 32) bsm[tid] = b[tid];
    __syncthreads();
    int v = blockIdx.x * 256 + tid;
    if (v >= N) return;
    float a[48];
    const float4* xr = (const float4*)(x + (size_t)v * 32);
#pragma unroll
    for (int k = 0; k < 8; k++) {
        float4 t4 = xr[k];
        a[4*k] = t4.x; a[4*k+1] = t4.y; a[4*k+2] = t4.z; a[4*k+3] = t4.w;
    }
    const float4* gr = (const float4*)(g_agg + (size_t)v * 16);
#pragma unroll
    for (int k = 0; k < 4; k++) {
        float4 t4 = gr[k];
        a[32+4*k] = t4.x; a[32+4*k+1] = t4.y; a[32+4*k+2] = t4.z; a[32+4*k+3] = t4.w;
    }
    GEMM32_BODY(48, g_n1 + (size_t)v * 32)
}

__global__ void k_own2(const float* __restrict__ w, const float* __restrict__ b,
                       const float* __restrict__ g1, const float* __restrict__ be1, int N) {
    __shared__ float wsm[1024], bsm[32], sc[32], sh[32];
    int tid = threadIdx.x;
    for (int t = tid; t < 1024; t += 256) wsm[t] = w[t];
    if (tid < 32) { bsm[tid] = b[tid]; bn_inline(2, g1, be1, (float)N, tid, sc, sh); }
    __syncthreads();
    int v = blockIdx.x * 256 + tid;
    if (v >= N) return;
    float a[32];
    const float4* ar = (const float4*)(g_n1 + (size_t)v * 32);
#pragma unroll
    for (int k = 0; k < 8; k++) {
        float4 t4 = ar[k];
        a[4*k+0] = fmaxf(t4.x * sc[4*k+0] + sh[4*k+0], 0.0f);
        a[4*k+1] = fmaxf(t4.y * sc[4*k+1] + sh[4*k+1], 0.0f);
        a[4*k+2] = fmaxf(t4.z * sc[4*k+2] + sh[4*k+2], 0.0f);
        a[4*k+3] = fmaxf(t4.w * sc[4*k+3] + sh[4*k+3], 0.0f);
    }
    GEMM32_BODY(32, g_n2 + (size_t)v * 32)
}

__global__ void k_own3(const float* __restrict__ w, const float* __restrict__ b,
                       const float* __restrict__ g2, const float* __restrict__ be2,
                       float* __restrict__ out, int N) {
    __shared__ float wsm[1024], bsm[32], sc[32], sh[32];
    int tid = threadIdx.x;
    for (int t = tid; t < 1024; t += 256) wsm[t] = w[t];
    if (tid < 32) { bsm[tid] = b[tid]; bn_inline(3, g2, be2, (float)N, tid, sc, sh); }
    __syncthreads();
    int v = blockIdx.x * 256 + tid;
    if (v >= N) return;
    float a[32];
    const float4* ar = (const float4*)(g_n2 + (size_t)v * 32);
#pragma unroll
    for (int k = 0; k < 8; k++) {
        float4 t4 = ar[k];
        a[4*k+0] = fmaxf(t4.x * sc[4*k+0] + sh[4*k+0], 0.0f);
        a[4*k+1] = fmaxf(t4.y * sc[4*k+1] + sh[4*k+1], 0.0f);
        a[4*k+2] = fmaxf(t4.z * sc[4*k+2] + sh[4*k+2], 0.0f);
        a[4*k+3] = fmaxf(t4.w * sc[4*k+3] + sh[4*k+3], 0.0f);
    }
    GEMM32_BODY(32, out + (size_t)v * 32)
}

extern "C" void kernel_launch(void* const* d_in, const int* in_sizes, int n_in,
                              void* d_out, int out_size) {
    const float* x    = (const float*)d_in[0];
    const float* ea   = (const float*)d_in[1];
    const void*  ei   = d_in[2];
    const float* mw1  = (const float*)d_in[3];
    const float* mb1  = (const float*)d_in[4];
    const float* mg1  = (const float*)d_in[5];
    const float* mbe1 = (const float*)d_in[6];
    const float* mw2  = (const float*)d_in[7];
    const float* mb2  = (const float*)d_in[8];
    const float* mg2  = (const float*)d_in[9];
    const float* mbe2 = (const float*)d_in[10];
    const float* mw3  = (const float*)d_in[11];
    const float* mb3  = (const float*)d_in[12];
    const float* rw   = (const float*)d_in[13];
    const float* rb   = (const float*)d_in[14];
    const float* ow1  = (const float*)d_in[15];
    const float* ob1  = (const float*)d_in[16];
    const float* og1  = (const float*)d_in[17];
    const float* obe1 = (const float*)d_in[18];
    const float* ow2  = (const float*)d_in[19];
    const float* ob2  = (const float*)d_in[20];
    const float* og2  = (const float*)d_in[21];
    const float* obe2 = (const float*)d_in[22];
    const float* ow3  = (const float*)d_in[23];
    const float* ob3  = (const float*)d_in[24];
    float* out = (float*)d_out;

    int  N = in_sizes[0] / SD;
    long E = (long)in_sizes[1] / SD;

    cudaFuncSetAttribute(k_T, cudaFuncAttributeMaxDynamicSharedMemorySize, 73856);

    int nb256  = (N + 255) / 256;
    long eb256 = (E + 255) / 256;
    long eb2   = (E + 511) / 512;
    long nu    = E * 4;

    k_init<<<nb256, 256>>>(ei, E, N, N, mw3);              // 1
    k_converthist<<<(unsigned)eb256, 256>>>(ei, E);        // 2
    k_scan<<<1, 1024>>>(N);                                // 3
    k_T<<<(N + 31) / 32, 256, 73856>>>(x, rw, rb, mb3, N); // 4: PROFILED (fused rootB)
    k_scatter<<<(unsigned)eb256, 256>>>(E);                // 5
    k_e1<<<(unsigned)eb2, 256>>>(ea, mw1, mb1, E);         // 6
    k_stath<<<296, 256>>>(0, nu, 0);
    k_e2<<<(unsigned)eb2, 256>>>(mw2, mb2, mg1, mbe1, E);
    k_stath<<<296, 256>>>(1, nu, 1);
    k_act<<<(unsigned)((nu + 255) / 256), 256>>>(mg2, mbe2, nu, (float)E);
    k_e3<<<1184, 256>>>(N);
    k_own1<<<nb256, 256>>>(x, ow1, ob1, N);
    k_stat<<<148, 256>>>(1, (long)N * 8, 2);
    k_own2<<<nb256, 256>>>(ow2, ob2, og1, obe1, N);
    k_stat<<<148, 256>>>(2, (long)N * 8, 3);
    k_own3<<<nb256, 256>>>(ow3, ob3, og2, obe2, out, N);
}